// round 15
// baseline (speedup 1.0000x reference)
#include <cuda_runtime.h>
#include <cuda_fp16.h>
#include <cstdint>

#define A_  4
#define B_  4
#define S_  2048
#define H_  1024
#define NH_ 16
#define HD_ 64
#define BS_ (B_ * S_)     // 8192
#define M1_ (BS_ * A_)    // 32768

// ---------------------------------------------------------------------------
// Scratch (device globals)
// ---------------------------------------------------------------------------
__device__ __align__(256) __half g_xh[M1_ * H_];        // 64 MB  (permuted x, fp16)
__device__ __align__(256) __half g_wTh[4][H_ * H_];     // 8 MB   (W^T [n][k], fp16)
__device__ __align__(256) __half g_ph[BS_ * H_];        // 16 MB  (pooled, fp16)
__device__ __align__(256) float g_fused[BS_ * H_];      // 32 MB

// ---------------------------------------------------------------------------
// PTX helpers (sm_80+ legal; no tcgen05 — base target rejects it)
// ---------------------------------------------------------------------------
__device__ __forceinline__ uint32_t smem_u32(const void* p) {
    uint32_t a;
    asm("{ .reg .u64 t; cvta.to.shared.u64 t, %1; cvt.u32.u64 %0, t; }" : "=r"(a) : "l"(p));
    return a;
}
__device__ __forceinline__ void cp16(uint32_t s, const void* g) {
    asm volatile("cp.async.cg.shared.global [%0], [%1], 16;" :: "r"(s), "l"(g));
}
__device__ __forceinline__ void cp_commit() {
    asm volatile("cp.async.commit_group;" ::: "memory");
}

#define LDM4(d, addr) \
    asm volatile("ldmatrix.sync.aligned.m8n8.x4.shared.b16 {%0,%1,%2,%3}, [%4];" \
                 : "=r"((d)[0]), "=r"((d)[1]), "=r"((d)[2]), "=r"((d)[3]) : "r"(addr))

#define MMA16816(d, a, b0v, b1v) \
    asm volatile("mma.sync.aligned.m16n8k16.row.col.f32.f16.f16.f32 " \
                 "{%0,%1,%2,%3}, {%4,%5,%6,%7}, {%8,%9}, {%0,%1,%2,%3};" \
                 : "+f"((d)[0]), "+f"((d)[1]), "+f"((d)[2]), "+f"((d)[3]) \
                 : "r"((a)[0]), "r"((a)[1]), "r"((a)[2]), "r"((a)[3]), \
                   "r"(b0v), "r"(b1v))

// SW128 swizzled offset of (row, 16B-chunk) within a 128B-row tile
__device__ __forceinline__ uint32_t swoff(int r, int c16) {
    return (uint32_t)(r * 128 + ((c16 ^ (r & 7)) << 4));
}

// ---------------------------------------------------------------------------
// Conversion kernels
// ---------------------------------------------------------------------------
// adapter [A,B,S,H] fp32 -> permuted rows m=bs*4+a, fp16.
// One block per bs (grid 8192), 4 rows/block, MLP=4 front-batched loads.
__global__ __launch_bounds__(256) void conv_x(const float* __restrict__ ad)
{
    const int bs = blockIdx.x;
    const int b = bs >> 11;
    const int s = bs & (S_ - 1);
    const int t = threadIdx.x;

    float4 v[A_];
#pragma unroll
    for (int a = 0; a < A_; a++) {
        const float* src = ad + ((size_t)((a * B_ + b) * S_) + s) * H_;
        v[a] = ((const float4*)src)[t];
    }
#pragma unroll
    for (int a = 0; a < A_; a++) {
        __half2* ph = (__half2*)&g_xh[(size_t)(bs * A_ + a) * H_ + t * 4];
        ph[0] = __floats2half2_rn(v[a].x, v[a].y);
        ph[1] = __floats2half2_rn(v[a].z, v[a].w);
    }
}

// W [k,n] fp32 -> W^T [n,k] fp16; blockIdx.z selects matrix
__global__ __launch_bounds__(256) void conv_w(const float* __restrict__ Wq,
                                              const float* __restrict__ Wk,
                                              const float* __restrict__ Wv,
                                              const float* __restrict__ Wo)
{
    const int z = blockIdx.z;
    const float* W = (z == 0) ? Wq : (z == 1) ? Wk : (z == 2) ? Wv : Wo;
    __half* oh = g_wTh[z];
    __shared__ float tl[32][33];
    const int tx = threadIdx.x, ty = threadIdx.y;
    const int n0 = blockIdx.x * 32, k0 = blockIdx.y * 32;
#pragma unroll
    for (int i = 0; i < 4; i++)
        tl[ty + 8 * i][tx] = W[(size_t)(k0 + ty + 8 * i) * H_ + n0 + tx];
    __syncthreads();
#pragma unroll
    for (int i = 0; i < 4; i++)
        oh[(size_t)(n0 + ty + 8 * i) * H_ + k0 + tx] = __float2half_rn(tl[tx][ty + 8 * i]);
}

// ---------------------------------------------------------------------------
// Fused QKV GEMM + attention + mean-pool (proven R7 config).
// CTA = (head h, 128-row m-block), 256 threads / 8 warps, warp tile 32x32.
// N=64 (one head), three 128x64 fp32 accumulators, 4-stage cp.async pipeline.
// ---------------------------------------------------------------------------
#define FA_OFF 0          // A tile: 128 x 64 fp16 = 16 KB
#define FB_OFF 16384      // 3 B tiles: 64 x 64 fp16 = 8 KB each
#define FSTAGE 40960      // 40 KB per stage
#define FNSTAGE 4
#define FDSMEM (FNSTAGE * FSTAGE + 1024)
#define QS_STRIDE 66      // padded fp32 row stride for attn smem overlay

__device__ __forceinline__ void f_load_chunk(uint32_t sb, int t, int mt, int h, int c)
{
    const int kof = c * 64;
#pragma unroll
    for (int i = 0; i < 4; i++) {                 // A: 1024 segs
        const int seg = t + i * 256;
        const int r = seg >> 3, c16 = seg & 7;
        cp16(sb + FA_OFF + swoff(r, c16),
             g_xh + (size_t)(mt * 128 + r) * H_ + kof + c16 * 8);
    }
#pragma unroll
    for (int z = 0; z < 3; z++)
#pragma unroll
        for (int i = 0; i < 2; i++) {             // B: 512 segs per matrix
            const int seg = t + i * 256;
            const int r = seg >> 3, c16 = seg & 7;
            cp16(sb + FB_OFF + z * 8192 + swoff(r, c16),
                 g_wTh[z] + (size_t)(h * 64 + r) * H_ + kof + c16 * 8);
        }
}

__global__ __launch_bounds__(256, 1)
void fused_qkv_attn(const float* __restrict__ bq, const float* __restrict__ bk,
                    const float* __restrict__ bv)
{
    extern __shared__ __align__(1024) char dsm[];
    const uint32_t sbase = (smem_u32(dsm) + 1023) & ~1023u;
    float* qsm = (float*)(dsm + ((1024 - (smem_u32(dsm) & 1023)) & 1023));
    float* ksm = qsm + 128 * QS_STRIDE;
    float* vsm = ksm + 128 * QS_STRIDE;

    const int t  = threadIdx.x;
    const int h  = blockIdx.x;    // head
    const int mt = blockIdx.y;    // 128-row m-block

    const int lane = t & 31;
    const int w  = t >> 5;        // 0..7
    const int wm = w >> 1;        // 0..3 (32 rows)
    const int wn = w & 1;         // 0..1 (32 cols)

    const int xorv = lane & 7;
    const uint32_t aOff = (uint32_t)((wm * 32 + ((lane >> 3) & 1) * 8 + (lane & 7)) * 128);
    const int aCk = lane >> 4;
    const uint32_t bOff = (uint32_t)((wn * 32 + ((lane >> 4) << 3) + (lane & 7)) * 128);
    const int bCk = (lane >> 3) & 1;

    float acc[3][2][4][4];        // [z][mi][ni][reg] = 96 regs
#pragma unroll
    for (int z = 0; z < 3; z++)
#pragma unroll
        for (int mi = 0; mi < 2; mi++)
#pragma unroll
            for (int ni = 0; ni < 4; ni++)
#pragma unroll
                for (int r = 0; r < 4; r++) acc[z][mi][ni][r] = 0.0f;

#pragma unroll
    for (int p = 0; p < FNSTAGE - 1; p++) {
        f_load_chunk(sbase + p * FSTAGE, t, mt, h, p);
        cp_commit();
    }

    const int NC = H_ / 64;   // 16
    for (int c = 0; c < NC; c++) {
        asm volatile("cp.async.wait_group %0;" :: "n"(FNSTAGE - 2) : "memory");
        __syncthreads();
        if (c + FNSTAGE - 1 < NC)
            f_load_chunk(sbase + ((c + FNSTAGE - 1) & (FNSTAGE - 1)) * FSTAGE,
                         t, mt, h, c + FNSTAGE - 1);
        cp_commit();   // unconditional: keeps group accounting

        const uint32_t sb = sbase + (c & (FNSTAGE - 1)) * FSTAGE;
#pragma unroll
        for (int ks = 0; ks < 4; ks++) {
            const uint32_t xa = (uint32_t)(((ks * 2 + aCk) ^ xorv) << 4);
            const uint32_t xb = (uint32_t)(((ks * 2 + bCk) ^ xorv) << 4);
            uint32_t ah[2][4];
#pragma unroll
            for (int mi = 0; mi < 2; mi++)
                LDM4(ah[mi], sb + FA_OFF + aOff + mi * 2048 + xa);
            uint32_t bh[3][4][2];
#pragma unroll
            for (int z = 0; z < 3; z++)
#pragma unroll
                for (int pi = 0; pi < 2; pi++) {
                    uint32_t tmp[4];
                    LDM4(tmp, sb + FB_OFF + z * 8192 + bOff + pi * 2048 + xb);
                    bh[z][2 * pi][0] = tmp[0]; bh[z][2 * pi][1] = tmp[1];
                    bh[z][2 * pi + 1][0] = tmp[2]; bh[z][2 * pi + 1][1] = tmp[3];
                }
#pragma unroll
            for (int z = 0; z < 3; z++)
#pragma unroll
                for (int mi = 0; mi < 2; mi++)
#pragma unroll
                    for (int ni = 0; ni < 4; ni++)
                        MMA16816(acc[z][mi][ni], ah[mi], bh[z][ni][0], bh[z][ni][1]);
        }
    }
    __syncthreads();   // pipeline smem done before overlay

    // Epilogue 1: accumulators (+bias) -> smem
    const float* biasp[3] = {bq, bk, bv};
#pragma unroll
    for (int z = 0; z < 3; z++) {
        float* dst = (z == 0) ? qsm : (z == 1) ? ksm : vsm;
#pragma unroll
        for (int mi = 0; mi < 2; mi++) {
            const int r0 = wm * 32 + mi * 16 + (lane >> 2);
#pragma unroll
            for (int ni = 0; ni < 4; ni++) {
                const int col = wn * 32 + ni * 8 + (lane & 3) * 2;
                const float2 bb = *(const float2*)(biasp[z] + h * 64 + col);
                float2 v01, v23;
                v01.x = acc[z][mi][ni][0] + bb.x; v01.y = acc[z][mi][ni][1] + bb.y;
                v23.x = acc[z][mi][ni][2] + bb.x; v23.y = acc[z][mi][ni][3] + bb.y;
                *(float2*)(dst + r0 * QS_STRIDE + col) = v01;
                *(float2*)(dst + (r0 + 8) * QS_STRIDE + col) = v23;
            }
        }
    }
    __syncthreads();

    // Epilogue 2: attention + mean pool (8 warps, 4 bs each)
#pragma unroll
    for (int g = 0; g < 4; g++) {
        const int lb = w * 4 + g;          // local bs 0..31
        float q[A_][2], k[A_][2], v[A_][2];
#pragma unroll
        for (int a = 0; a < A_; a++) {
            const int row = lb * 4 + a;
            q[a][0] = qsm[row * QS_STRIDE + lane];
            q[a][1] = qsm[row * QS_STRIDE + lane + 32];
            k[a][0] = ksm[row * QS_STRIDE + lane];
            k[a][1] = ksm[row * QS_STRIDE + lane + 32];
            v[a][0] = vsm[row * QS_STRIDE + lane];
            v[a][1] = vsm[row * QS_STRIDE + lane + 32];
        }
        float sc[A_][A_];
#pragma unroll
        for (int i = 0; i < A_; i++)
#pragma unroll
            for (int j = 0; j < A_; j++)
                sc[i][j] = q[i][0] * k[j][0] + q[i][1] * k[j][1];
#pragma unroll
        for (int off = 16; off > 0; off >>= 1)
#pragma unroll
            for (int i = 0; i < A_; i++)
#pragma unroll
                for (int j = 0; j < A_; j++)
                    sc[i][j] += __shfl_xor_sync(0xffffffffu, sc[i][j], off);

        float colw[A_] = {0.f, 0.f, 0.f, 0.f};
#pragma unroll
        for (int i = 0; i < A_; i++) {
            float s0 = sc[i][0] * 0.125f, s1 = sc[i][1] * 0.125f;
            float s2 = sc[i][2] * 0.125f, s3 = sc[i][3] * 0.125f;
            const float mx = fmaxf(fmaxf(s0, s1), fmaxf(s2, s3));
            const float e0 = __expf(s0 - mx), e1 = __expf(s1 - mx);
            const float e2 = __expf(s2 - mx), e3 = __expf(s3 - mx);
            const float inv = 1.0f / (e0 + e1 + e2 + e3);
            colw[0] += e0 * inv; colw[1] += e1 * inv;
            colw[2] += e2 * inv; colw[3] += e3 * inv;
        }
        float o0 = 0.f, o1 = 0.f;
#pragma unroll
        for (int j = 0; j < A_; j++) {
            const float cc = colw[j] * 0.25f;
            o0 = fmaf(cc, v[j][0], o0);
            o1 = fmaf(cc, v[j][1], o1);
        }
        const int bs = mt * 32 + lb;
        __half* op = g_ph + (size_t)bs * H_ + h * 64;
        op[lane]      = __float2half_rn(o0);
        op[lane + 32] = __float2half_rn(o1);
    }
}

// ---------------------------------------------------------------------------
// O-projection GEMM: g_fused = g_ph . WoT + bo + resid (adapter[0]).
// CTA 64x128, 256 threads / 8 warps (2x4), warp tile 32x32, 4-stage pipe,
// 97 KB smem + <=128 regs -> 2 CTAs/SM, 1024 CTAs (fine tail).
// ---------------------------------------------------------------------------
#define OA_OFF 0
#define OB_OFF 8192
#define OSTAGE 24576
#define ODSMEM (4 * OSTAGE + 1024)   // 99328

__device__ __forceinline__ void o_load_chunk(uint32_t sb, int t, int mt, int nt, int c)
{
    const int kof = c * 64;
#pragma unroll
    for (int i = 0; i < 2; i++) {          // A: 512 segs (64 rows)
        const int seg = t + i * 256;
        const int r = seg >> 3, c16 = seg & 7;
        cp16(sb + OA_OFF + swoff(r, c16),
             g_ph + (size_t)(mt * 64 + r) * H_ + kof + c16 * 8);
    }
#pragma unroll
    for (int i = 0; i < 4; i++) {          // B: 1024 segs (128 rows)
        const int seg = t + i * 256;
        const int r = seg >> 3, c16 = seg & 7;
        cp16(sb + OB_OFF + swoff(r, c16),
             g_wTh[3] + (size_t)(nt * 128 + r) * H_ + kof + c16 * 8);
    }
}

__global__ __launch_bounds__(256, 2)
void gemm_o(const float* __restrict__ bias, const float* __restrict__ resid)
{
    extern __shared__ __align__(1024) char dsm[];
    const uint32_t sbase = (smem_u32(dsm) + 1023) & ~1023u;

    const int t  = threadIdx.x;
    const int nt = blockIdx.x;
    const int mt = blockIdx.y;

    const int lane = t & 31;
    const int w  = t >> 5;        // 0..7
    const int wm = w >> 2;        // 0..1 (32 rows)
    const int wn = w & 3;         // 0..3 (32 cols)

    const int xorv = lane & 7;
    const uint32_t aOff = (uint32_t)((wm * 32 + ((lane >> 3) & 1) * 8 + (lane & 7)) * 128);
    const int aCk = lane >> 4;
    const uint32_t bOff = (uint32_t)((wn * 32 + ((lane >> 4) << 3) + (lane & 7)) * 128);
    const int bCk = (lane >> 3) & 1;

    float acc[2][4][4];   // 32 regs
#pragma unroll
    for (int mi = 0; mi < 2; mi++)
#pragma unroll
        for (int ni = 0; ni < 4; ni++)
#pragma unroll
            for (int r = 0; r < 4; r++) acc[mi][ni][r] = 0.0f;

#pragma unroll
    for (int p = 0; p < 3; p++) {
        o_load_chunk(sbase + p * OSTAGE, t, mt, nt, p);
        cp_commit();
    }

    const int NC = H_ / 64;
    for (int c = 0; c < NC; c++) {
        asm volatile("cp.async.wait_group 2;" ::: "memory");
        __syncthreads();
        if (c + 3 < NC)
            o_load_chunk(sbase + ((c + 3) & 3) * OSTAGE, t, mt, nt, c + 3);
        cp_commit();

        const uint32_t sb = sbase + (c & 3) * OSTAGE;
#pragma unroll
        for (int ks = 0; ks < 4; ks++) {
            uint32_t ah[2][4], bh[4][2];
            const uint32_t xa = (uint32_t)(((ks * 2 + aCk) ^ xorv) << 4);
            const uint32_t xb = (uint32_t)(((ks * 2 + bCk) ^ xorv) << 4);
#pragma unroll
            for (int mi = 0; mi < 2; mi++)
                LDM4(ah[mi], sb + OA_OFF + aOff + mi * 2048 + xa);
#pragma unroll
            for (int pi = 0; pi < 2; pi++) {
                uint32_t tmp[4];
                LDM4(tmp, sb + OB_OFF + bOff + pi * 2048 + xb);
                bh[2 * pi][0] = tmp[0]; bh[2 * pi][1] = tmp[1];
                bh[2 * pi + 1][0] = tmp[2]; bh[2 * pi + 1][1] = tmp[3];
            }
#pragma unroll
            for (int mi = 0; mi < 2; mi++)
#pragma unroll
                for (int ni = 0; ni < 4; ni++)
                    MMA16816(acc[mi][ni], ah[mi], bh[ni][0], bh[ni][1]);
        }
    }

#pragma unroll
    for (int mi = 0; mi < 2; mi++) {
        const int r0 = mt * 64 + wm * 32 + mi * 16 + (lane >> 2);
        const int r1 = r0 + 8;
#pragma unroll
        for (int ni = 0; ni < 4; ni++) {
            const int col = nt * 128 + wn * 32 + ni * 8 + (lane & 3) * 2;
            const float2 bb = *(const float2*)(bias + col);
            const float2 ra = *(const float2*)(resid + (size_t)r0 * H_ + col);
            const float2 rb = *(const float2*)(resid + (size_t)r1 * H_ + col);
            float2 v01, v23;
            v01.x = acc[mi][ni][0] + bb.x + ra.x; v01.y = acc[mi][ni][1] + bb.y + ra.y;
            v23.x = acc[mi][ni][2] + bb.x + rb.x; v23.y = acc[mi][ni][3] + bb.y + rb.y;
            *(float2*)(g_fused + (size_t)r0 * H_ + col) = v01;
            *(float2*)(g_fused + (size_t)r1 * H_ + col) = v23;
        }
    }
}

// ---------------------------------------------------------------------------
// LayerNorm over H=1024 per row
// ---------------------------------------------------------------------------
__global__ __launch_bounds__(256)
void ln_kernel(const float* __restrict__ gamma,
               const float* __restrict__ beta,
               float* __restrict__ out)
{
    const int row = blockIdx.x;
    const int t = threadIdx.x;

    const float4 x = ((const float4*)(g_fused + (size_t)row * H_))[t];
    float s  = x.x + x.y + x.z + x.w;
    float ss = x.x * x.x + x.y * x.y + x.z * x.z + x.w * x.w;
#pragma unroll
    for (int off = 16; off > 0; off >>= 1) {
        s  += __shfl_xor_sync(0xffffffffu, s,  off);
        ss += __shfl_xor_sync(0xffffffffu, ss, off);
    }
    __shared__ float sh_s[8], sh_ss[8];
    if ((t & 31) == 0) { sh_s[t >> 5] = s; sh_ss[t >> 5] = ss; }
    __syncthreads();
    float tot = 0.f, tot2 = 0.f;
#pragma unroll
    for (int w = 0; w < 8; w++) { tot += sh_s[w]; tot2 += sh_ss[w]; }

    const float mu   = tot * (1.0f / H_);
    const float var  = tot2 * (1.0f / H_) - mu * mu;
    const float rstd = rsqrtf(var + 1e-5f);

    const float4 g = ((const float4*)gamma)[t];
    const float4 b = ((const float4*)beta)[t];
    float4 y;
    y.x = (x.x - mu) * rstd * g.x + b.x;
    y.y = (x.y - mu) * rstd * g.y + b.y;
    y.z = (x.z - mu) * rstd * g.z + b.z;
    y.w = (x.w - mu) * rstd * g.w + b.w;
    ((float4*)(out + (size_t)row * H_))[t] = y;
}

// ---------------------------------------------------------------------------
// Launch
// ---------------------------------------------------------------------------
extern "C" void kernel_launch(void* const* d_in, const int* in_sizes, int n_in,
                              void* d_out, int out_size)
{
    (void)in_sizes; (void)n_in; (void)out_size;
    const float* adapter = (const float*)d_in[0];
    const float* Wq = (const float*)d_in[1];
    const float* bq = (const float*)d_in[2];
    const float* Wk = (const float*)d_in[3];
    const float* bk = (const float*)d_in[4];
    const float* Wv = (const float*)d_in[5];
    const float* bv = (const float*)d_in[6];
    const float* Wo = (const float*)d_in[7];
    const float* bo = (const float*)d_in[8];
    const float* gamma = (const float*)d_in[9];
    const float* beta  = (const float*)d_in[10];
    float* out = (float*)d_out;

    cudaFuncSetAttribute(fused_qkv_attn, cudaFuncAttributeMaxDynamicSharedMemorySize, FDSMEM);
    cudaFuncSetAttribute(gemm_o, cudaFuncAttributeMaxDynamicSharedMemorySize, ODSMEM);

    conv_x<<<BS_, 256>>>(adapter);
    conv_w<<<dim3(32, 32, 4), dim3(32, 8)>>>(Wq, Wk, Wv, Wo);

    const dim3 gf(NH_, M1_ / 128);    // (16 heads, 256 m-blocks)
    fused_qkv_attn<<<gf, 256, FDSMEM>>>(bq, bk, bv);

    const dim3 go(H_ / 128, BS_ / 64);   // (8, 128)
    gemm_o<<<go, 256, ODSMEM>>>(bo, adapter);

    ln_kernel<<<BS_, 256>>>(gamma, beta, out);
}

// round 16
// speedup vs baseline: 1.0719x; 1.0719x over previous
#include <cuda_runtime.h>
#include <cuda_fp16.h>
#include <cstdint>

#define A_  4
#define B_  4
#define S_  2048
#define H_  1024
#define NH_ 16
#define HD_ 64
#define BS_ (B_ * S_)     // 8192
#define M1_ (BS_ * A_)    // 32768

// ---------------------------------------------------------------------------
// Scratch (device globals)
// ---------------------------------------------------------------------------
__device__ __align__(256) __half g_xh[M1_ * H_];        // 64 MB  (permuted x, fp16)
__device__ __align__(256) __half g_wTh[4][H_ * H_];     // 8 MB   (W^T [n][k], fp16)
__device__ __align__(256) __half g_ph[BS_ * H_];        // 16 MB  (pooled, fp16)
__device__ __align__(256) float g_fused[BS_ * H_];      // 32 MB

// ---------------------------------------------------------------------------
// PTX helpers (sm_80+ legal; no tcgen05 — base target rejects it)
// ---------------------------------------------------------------------------
__device__ __forceinline__ uint32_t smem_u32(const void* p) {
    uint32_t a;
    asm("{ .reg .u64 t; cvta.to.shared.u64 t, %1; cvt.u32.u64 %0, t; }" : "=r"(a) : "l"(p));
    return a;
}
__device__ __forceinline__ void cp16(uint32_t s, const void* g) {
    asm volatile("cp.async.cg.shared.global [%0], [%1], 16;" :: "r"(s), "l"(g));
}
__device__ __forceinline__ void cp_commit() {
    asm volatile("cp.async.commit_group;" ::: "memory");
}

#define LDM4(d, addr) \
    asm volatile("ldmatrix.sync.aligned.m8n8.x4.shared.b16 {%0,%1,%2,%3}, [%4];" \
                 : "=r"((d)[0]), "=r"((d)[1]), "=r"((d)[2]), "=r"((d)[3]) : "r"(addr))

#define MMA16816(d, a, b0v, b1v) \
    asm volatile("mma.sync.aligned.m16n8k16.row.col.f32.f16.f16.f32 " \
                 "{%0,%1,%2,%3}, {%4,%5,%6,%7}, {%8,%9}, {%0,%1,%2,%3};" \
                 : "+f"((d)[0]), "+f"((d)[1]), "+f"((d)[2]), "+f"((d)[3]) \
                 : "r"((a)[0]), "r"((a)[1]), "r"((a)[2]), "r"((a)[3]), \
                   "r"(b0v), "r"(b1v))

// SW128 swizzled offset of (row, 16B-chunk) within a 128B-row tile
__device__ __forceinline__ uint32_t swoff(int r, int c16) {
    return (uint32_t)(r * 128 + ((c16 ^ (r & 7)) << 4));
}

// ---------------------------------------------------------------------------
// Conversion kernels
// ---------------------------------------------------------------------------
// adapter [A,B,S,H] fp32 -> permuted rows m=bs*4+a, fp16.
// One block per bs (grid 8192), 4 rows/block, MLP=4 front-batched loads.
__global__ __launch_bounds__(256) void conv_x(const float* __restrict__ ad)
{
    const int bs = blockIdx.x;
    const int b = bs >> 11;
    const int s = bs & (S_ - 1);
    const int t = threadIdx.x;

    float4 v[A_];
#pragma unroll
    for (int a = 0; a < A_; a++) {
        const float* src = ad + ((size_t)((a * B_ + b) * S_) + s) * H_;
        v[a] = ((const float4*)src)[t];
    }
#pragma unroll
    for (int a = 0; a < A_; a++) {
        __half2* ph = (__half2*)&g_xh[(size_t)(bs * A_ + a) * H_ + t * 4];
        ph[0] = __floats2half2_rn(v[a].x, v[a].y);
        ph[1] = __floats2half2_rn(v[a].z, v[a].w);
    }
}

// W [k,n] fp32 -> W^T [n,k] fp16; blockIdx.z selects matrix
__global__ __launch_bounds__(256) void conv_w(const float* __restrict__ Wq,
                                              const float* __restrict__ Wk,
                                              const float* __restrict__ Wv,
                                              const float* __restrict__ Wo)
{
    const int z = blockIdx.z;
    const float* W = (z == 0) ? Wq : (z == 1) ? Wk : (z == 2) ? Wv : Wo;
    __half* oh = g_wTh[z];
    __shared__ float tl[32][33];
    const int tx = threadIdx.x, ty = threadIdx.y;
    const int n0 = blockIdx.x * 32, k0 = blockIdx.y * 32;
#pragma unroll
    for (int i = 0; i < 4; i++)
        tl[ty + 8 * i][tx] = W[(size_t)(k0 + ty + 8 * i) * H_ + n0 + tx];
    __syncthreads();
#pragma unroll
    for (int i = 0; i < 4; i++)
        oh[(size_t)(n0 + ty + 8 * i) * H_ + k0 + tx] = __float2half_rn(tl[tx][ty + 8 * i]);
}

// ---------------------------------------------------------------------------
// Fused QKV GEMM + attention + mean-pool, 2 CTAs/SM variant.
// CTA = (head h, 64-row m-block), 256 threads / 8 warps, warp tile 32x16,
// three accumulators (Q,K,V), 3-stage cp.async ring (32 KB/stage = 96 KB).
// ---------------------------------------------------------------------------
#define FA_OFF 0          // A tile: 64 x 64 fp16 = 8 KB
#define FB_OFF 8192       // 3 B tiles: 64 x 64 fp16 = 8 KB each
#define FSTAGE 32768      // 32 KB per stage
#define FDSMEM (3 * FSTAGE + 1024)   // 99328; attn overlay (50.7 KB) aliases
#define QS_STRIDE 66      // padded fp32 row stride for attn smem overlay

__device__ __forceinline__ void f_load_chunk(uint32_t sb, int t, int mt, int h, int c)
{
    const int kof = c * 64;
#pragma unroll
    for (int i = 0; i < 2; i++) {                 // A: 512 segs (64 rows)
        const int seg = t + i * 256;
        const int r = seg >> 3, c16 = seg & 7;
        cp16(sb + FA_OFF + swoff(r, c16),
             g_xh + (size_t)(mt * 64 + r) * H_ + kof + c16 * 8);
    }
#pragma unroll
    for (int z = 0; z < 3; z++)
#pragma unroll
        for (int i = 0; i < 2; i++) {             // B: 512 segs per matrix
            const int seg = t + i * 256;
            const int r = seg >> 3, c16 = seg & 7;
            cp16(sb + FB_OFF + z * 8192 + swoff(r, c16),
                 g_wTh[z] + (size_t)(h * 64 + r) * H_ + kof + c16 * 8);
        }
}

__global__ __launch_bounds__(256, 2)
void fused_qkv_attn(const float* __restrict__ bq, const float* __restrict__ bk,
                    const float* __restrict__ bv)
{
    extern __shared__ __align__(1024) char dsm[];
    const uint32_t sbase = (smem_u32(dsm) + 1023) & ~1023u;
    float* qsm = (float*)(dsm + ((1024 - (smem_u32(dsm) & 1023)) & 1023));
    float* ksm = qsm + 64 * QS_STRIDE;
    float* vsm = ksm + 64 * QS_STRIDE;

    const int t  = threadIdx.x;
    const int h  = blockIdx.x;    // head
    const int mt = blockIdx.y;    // 64-row m-block

    const int lane = t & 31;
    const int w  = t >> 5;        // 0..7
    const int wm = w >> 2;        // 0..1 (32 rows)
    const int wn = w & 3;         // 0..3 (16 cols)

    const int xorv = lane & 7;
    const uint32_t aOff = (uint32_t)((wm * 32 + ((lane >> 3) & 1) * 8 + (lane & 7)) * 128);
    const int aCk = lane >> 4;
    const uint32_t bOff = (uint32_t)((wn * 16 + ((lane >> 4) << 3) + (lane & 7)) * 128);
    const int bCk = (lane >> 3) & 1;

    float acc[3][2][2][4];        // [z][mi][ni][reg] = 48 regs
#pragma unroll
    for (int z = 0; z < 3; z++)
#pragma unroll
        for (int mi = 0; mi < 2; mi++)
#pragma unroll
            for (int ni = 0; ni < 2; ni++)
#pragma unroll
                for (int r = 0; r < 4; r++) acc[z][mi][ni][r] = 0.0f;

    // prologue: stages 0,1 <- chunks 0,1
    f_load_chunk(sbase, t, mt, h, 0);
    cp_commit();
    f_load_chunk(sbase + FSTAGE, t, mt, h, 1);
    cp_commit();

    int st_c = 0;   // compute stage for chunk c
    int st_l = 2;   // load stage for chunk c+2
    const int NC = H_ / 64;   // 16
    for (int c = 0; c < NC; c++) {
        asm volatile("cp.async.wait_group 1;" ::: "memory");   // chunk c resident
        __syncthreads();
        if (c + 2 < NC)
            f_load_chunk(sbase + st_l * FSTAGE, t, mt, h, c + 2);
        cp_commit();   // unconditional: keeps group accounting

        const uint32_t sb = sbase + st_c * FSTAGE;
        st_c = (st_c == 2) ? 0 : st_c + 1;
        st_l = (st_l == 2) ? 0 : st_l + 1;
#pragma unroll
        for (int ks = 0; ks < 4; ks++) {
            const uint32_t xa = (uint32_t)(((ks * 2 + aCk) ^ xorv) << 4);
            const uint32_t xb = (uint32_t)(((ks * 2 + bCk) ^ xorv) << 4);
            uint32_t ah[2][4];
#pragma unroll
            for (int mi = 0; mi < 2; mi++)
                LDM4(ah[mi], sb + FA_OFF + aOff + mi * 2048 + xa);
            uint32_t bh[3][2][2];
#pragma unroll
            for (int z = 0; z < 3; z++) {
                uint32_t tmp[4];
                LDM4(tmp, sb + FB_OFF + z * 8192 + bOff + xb);
                bh[z][0][0] = tmp[0]; bh[z][0][1] = tmp[1];
                bh[z][1][0] = tmp[2]; bh[z][1][1] = tmp[3];
            }
#pragma unroll
            for (int z = 0; z < 3; z++)
#pragma unroll
                for (int mi = 0; mi < 2; mi++)
#pragma unroll
                    for (int ni = 0; ni < 2; ni++)
                        MMA16816(acc[z][mi][ni], ah[mi], bh[z][ni][0], bh[z][ni][1]);
        }
    }
    __syncthreads();   // pipeline smem done before overlay

    // Epilogue 1: accumulators (+bias) -> smem (64 x 64 per matrix)
    const float* biasp[3] = {bq, bk, bv};
#pragma unroll
    for (int z = 0; z < 3; z++) {
        float* dst = (z == 0) ? qsm : (z == 1) ? ksm : vsm;
#pragma unroll
        for (int mi = 0; mi < 2; mi++) {
            const int r0 = wm * 32 + mi * 16 + (lane >> 2);
#pragma unroll
            for (int ni = 0; ni < 2; ni++) {
                const int col = wn * 16 + ni * 8 + (lane & 3) * 2;
                const float2 bb = *(const float2*)(biasp[z] + h * 64 + col);
                float2 v01, v23;
                v01.x = acc[z][mi][ni][0] + bb.x; v01.y = acc[z][mi][ni][1] + bb.y;
                v23.x = acc[z][mi][ni][2] + bb.x; v23.y = acc[z][mi][ni][3] + bb.y;
                *(float2*)(dst + r0 * QS_STRIDE + col) = v01;
                *(float2*)(dst + (r0 + 8) * QS_STRIDE + col) = v23;
            }
        }
    }
    __syncthreads();

    // Epilogue 2: attention + mean pool (16 bs per CTA; 8 warps, 2 bs each)
#pragma unroll
    for (int g = 0; g < 2; g++) {
        const int lb = w * 2 + g;          // local bs 0..15
        float q[A_][2], k[A_][2], v[A_][2];
#pragma unroll
        for (int a = 0; a < A_; a++) {
            const int row = lb * 4 + a;    // 0..63
            q[a][0] = qsm[row * QS_STRIDE + lane];
            q[a][1] = qsm[row * QS_STRIDE + lane + 32];
            k[a][0] = ksm[row * QS_STRIDE + lane];
            k[a][1] = ksm[row * QS_STRIDE + lane + 32];
            v[a][0] = vsm[row * QS_STRIDE + lane];
            v[a][1] = vsm[row * QS_STRIDE + lane + 32];
        }
        float sc[A_][A_];
#pragma unroll
        for (int i = 0; i < A_; i++)
#pragma unroll
            for (int j = 0; j < A_; j++)
                sc[i][j] = q[i][0] * k[j][0] + q[i][1] * k[j][1];
#pragma unroll
        for (int off = 16; off > 0; off >>= 1)
#pragma unroll
            for (int i = 0; i < A_; i++)
#pragma unroll
                for (int j = 0; j < A_; j++)
                    sc[i][j] += __shfl_xor_sync(0xffffffffu, sc[i][j], off);

        float colw[A_] = {0.f, 0.f, 0.f, 0.f};
#pragma unroll
        for (int i = 0; i < A_; i++) {
            float s0 = sc[i][0] * 0.125f, s1 = sc[i][1] * 0.125f;
            float s2 = sc[i][2] * 0.125f, s3 = sc[i][3] * 0.125f;
            const float mx = fmaxf(fmaxf(s0, s1), fmaxf(s2, s3));
            const float e0 = __expf(s0 - mx), e1 = __expf(s1 - mx);
            const float e2 = __expf(s2 - mx), e3 = __expf(s3 - mx);
            const float inv = 1.0f / (e0 + e1 + e2 + e3);
            colw[0] += e0 * inv; colw[1] += e1 * inv;
            colw[2] += e2 * inv; colw[3] += e3 * inv;
        }
        float o0 = 0.f, o1 = 0.f;
#pragma unroll
        for (int j = 0; j < A_; j++) {
            const float cc = colw[j] * 0.25f;
            o0 = fmaf(cc, v[j][0], o0);
            o1 = fmaf(cc, v[j][1], o1);
        }
        const int bs = mt * 16 + lb;
        __half* op = g_ph + (size_t)bs * H_ + h * 64;
        op[lane]      = __float2half_rn(o0);
        op[lane + 32] = __float2half_rn(o1);
    }
}

// ---------------------------------------------------------------------------
// O-projection GEMM: g_fused = g_ph . WoT + bo + resid (adapter[0]).
// CTA 64x128, 256 threads / 8 warps (2x4), warp tile 32x32, 4-stage pipe,
// 97 KB smem + <=128 regs -> 2 CTAs/SM, 1024 CTAs (fine tail).
// ---------------------------------------------------------------------------
#define OA_OFF 0
#define OB_OFF 8192
#define OSTAGE 24576
#define ODSMEM (4 * OSTAGE + 1024)   // 99328

__device__ __forceinline__ void o_load_chunk(uint32_t sb, int t, int mt, int nt, int c)
{
    const int kof = c * 64;
#pragma unroll
    for (int i = 0; i < 2; i++) {          // A: 512 segs (64 rows)
        const int seg = t + i * 256;
        const int r = seg >> 3, c16 = seg & 7;
        cp16(sb + OA_OFF + swoff(r, c16),
             g_ph + (size_t)(mt * 64 + r) * H_ + kof + c16 * 8);
    }
#pragma unroll
    for (int i = 0; i < 4; i++) {          // B: 1024 segs (128 rows)
        const int seg = t + i * 256;
        const int r = seg >> 3, c16 = seg & 7;
        cp16(sb + OB_OFF + swoff(r, c16),
             g_wTh[3] + (size_t)(nt * 128 + r) * H_ + kof + c16 * 8);
    }
}

__global__ __launch_bounds__(256, 2)
void gemm_o(const float* __restrict__ bias, const float* __restrict__ resid)
{
    extern __shared__ __align__(1024) char dsm[];
    const uint32_t sbase = (smem_u32(dsm) + 1023) & ~1023u;

    const int t  = threadIdx.x;
    const int nt = blockIdx.x;
    const int mt = blockIdx.y;

    const int lane = t & 31;
    const int w  = t >> 5;        // 0..7
    const int wm = w >> 2;        // 0..1 (32 rows)
    const int wn = w & 3;         // 0..3 (32 cols)

    const int xorv = lane & 7;
    const uint32_t aOff = (uint32_t)((wm * 32 + ((lane >> 3) & 1) * 8 + (lane & 7)) * 128);
    const int aCk = lane >> 4;
    const uint32_t bOff = (uint32_t)((wn * 32 + ((lane >> 4) << 3) + (lane & 7)) * 128);
    const int bCk = (lane >> 3) & 1;

    float acc[2][4][4];   // 32 regs
#pragma unroll
    for (int mi = 0; mi < 2; mi++)
#pragma unroll
        for (int ni = 0; ni < 4; ni++)
#pragma unroll
            for (int r = 0; r < 4; r++) acc[mi][ni][r] = 0.0f;

#pragma unroll
    for (int p = 0; p < 3; p++) {
        o_load_chunk(sbase + p * OSTAGE, t, mt, nt, p);
        cp_commit();
    }

    const int NC = H_ / 64;
    for (int c = 0; c < NC; c++) {
        asm volatile("cp.async.wait_group 2;" ::: "memory");
        __syncthreads();
        if (c + 3 < NC)
            o_load_chunk(sbase + ((c + 3) & 3) * OSTAGE, t, mt, nt, c + 3);
        cp_commit();

        const uint32_t sb = sbase + (c & 3) * OSTAGE;
#pragma unroll
        for (int ks = 0; ks < 4; ks++) {
            uint32_t ah[2][4], bh[4][2];
            const uint32_t xa = (uint32_t)(((ks * 2 + aCk) ^ xorv) << 4);
            const uint32_t xb = (uint32_t)(((ks * 2 + bCk) ^ xorv) << 4);
#pragma unroll
            for (int mi = 0; mi < 2; mi++)
                LDM4(ah[mi], sb + OA_OFF + aOff + mi * 2048 + xa);
#pragma unroll
            for (int pi = 0; pi < 2; pi++) {
                uint32_t tmp[4];
                LDM4(tmp, sb + OB_OFF + bOff + pi * 2048 + xb);
                bh[2 * pi][0] = tmp[0]; bh[2 * pi][1] = tmp[1];
                bh[2 * pi + 1][0] = tmp[2]; bh[2 * pi + 1][1] = tmp[3];
            }
#pragma unroll
            for (int mi = 0; mi < 2; mi++)
#pragma unroll
                for (int ni = 0; ni < 4; ni++)
                    MMA16816(acc[mi][ni], ah[mi], bh[ni][0], bh[ni][1]);
        }
    }

#pragma unroll
    for (int mi = 0; mi < 2; mi++) {
        const int r0 = mt * 64 + wm * 32 + mi * 16 + (lane >> 2);
        const int r1 = r0 + 8;
#pragma unroll
        for (int ni = 0; ni < 4; ni++) {
            const int col = nt * 128 + wn * 32 + ni * 8 + (lane & 3) * 2;
            const float2 bb = *(const float2*)(bias + col);
            const float2 ra = *(const float2*)(resid + (size_t)r0 * H_ + col);
            const float2 rb = *(const float2*)(resid + (size_t)r1 * H_ + col);
            float2 v01, v23;
            v01.x = acc[mi][ni][0] + bb.x + ra.x; v01.y = acc[mi][ni][1] + bb.y + ra.y;
            v23.x = acc[mi][ni][2] + bb.x + rb.x; v23.y = acc[mi][ni][3] + bb.y + rb.y;
            *(float2*)(g_fused + (size_t)r0 * H_ + col) = v01;
            *(float2*)(g_fused + (size_t)r1 * H_ + col) = v23;
        }
    }
}

// ---------------------------------------------------------------------------
// LayerNorm over H=1024 per row
// ---------------------------------------------------------------------------
__global__ __launch_bounds__(256)
void ln_kernel(const float* __restrict__ gamma,
               const float* __restrict__ beta,
               float* __restrict__ out)
{
    const int row = blockIdx.x;
    const int t = threadIdx.x;

    const float4 x = ((const float4*)(g_fused + (size_t)row * H_))[t];
    float s  = x.x + x.y + x.z + x.w;
    float ss = x.x * x.x + x.y * x.y + x.z * x.z + x.w * x.w;
#pragma unroll
    for (int off = 16; off > 0; off >>= 1) {
        s  += __shfl_xor_sync(0xffffffffu, s,  off);
        ss += __shfl_xor_sync(0xffffffffu, ss, off);
    }
    __shared__ float sh_s[8], sh_ss[8];
    if ((t & 31) == 0) { sh_s[t >> 5] = s; sh_ss[t >> 5] = ss; }
    __syncthreads();
    float tot = 0.f, tot2 = 0.f;
#pragma unroll
    for (int w = 0; w < 8; w++) { tot += sh_s[w]; tot2 += sh_ss[w]; }

    const float mu   = tot * (1.0f / H_);
    const float var  = tot2 * (1.0f / H_) - mu * mu;
    const float rstd = rsqrtf(var + 1e-5f);

    const float4 g = ((const float4*)gamma)[t];
    const float4 b = ((const float4*)beta)[t];
    float4 y;
    y.x = (x.x - mu) * rstd * g.x + b.x;
    y.y = (x.y - mu) * rstd * g.y + b.y;
    y.z = (x.z - mu) * rstd * g.z + b.z;
    y.w = (x.w - mu) * rstd * g.w + b.w;
    ((float4*)(out + (size_t)row * H_))[t] = y;
}

// ---------------------------------------------------------------------------
// Launch
// ---------------------------------------------------------------------------
extern "C" void kernel_launch(void* const* d_in, const int* in_sizes, int n_in,
                              void* d_out, int out_size)
{
    (void)in_sizes; (void)n_in; (void)out_size;
    const float* adapter = (const float*)d_in[0];
    const float* Wq = (const float*)d_in[1];
    const float* bq = (const float*)d_in[2];
    const float* Wk = (const float*)d_in[3];
    const float* bk = (const float*)d_in[4];
    const float* Wv = (const float*)d_in[5];
    const float* bv = (const float*)d_in[6];
    const float* Wo = (const float*)d_in[7];
    const float* bo = (const float*)d_in[8];
    const float* gamma = (const float*)d_in[9];
    const float* beta  = (const float*)d_in[10];
    float* out = (float*)d_out;

    cudaFuncSetAttribute(fused_qkv_attn, cudaFuncAttributeMaxDynamicSharedMemorySize, FDSMEM);
    cudaFuncSetAttribute(gemm_o, cudaFuncAttributeMaxDynamicSharedMemorySize, ODSMEM);

    conv_x<<<BS_, 256>>>(adapter);
    conv_w<<<dim3(32, 32, 4), dim3(32, 8)>>>(Wq, Wk, Wv, Wo);

    const dim3 gf(NH_, M1_ / 64);     // (16 heads, 512 m-blocks)
    fused_qkv_attn<<<gf, 256, FDSMEM>>>(bq, bk, bv);

    const dim3 go(H_ / 128, BS_ / 64);   // (8, 128)
    gemm_o<<<go, 256, ODSMEM>>>(bo, adapter);

    ln_kernel<<<BS_, 256>>>(gamma, beta, out);
}